// round 3
// baseline (speedup 1.0000x reference)
#include <cuda_runtime.h>
#include <math.h>

// ---------------------------------------------------------------------------
// PathGuidedAggregator: S=8192 nodes x P=16 paths x K=16 endpoints, D=128, H=64
// Round 2: Phase-B GEMM register tiling (2 paths x 4 j x split-K 4) to cut
// shared-memory crossbar traffic (W1 reread) ~4x. Bank-conflict-free layouts
// via sAgg stride 132 and sPart path-stride 33.
// ---------------------------------------------------------------------------

#define DD 128
#define PP 16
#define KK 16
#define HH 64
#define AGG_STRIDE 132           // floats per sAgg row (pad kills 8-way conflicts)
#define PART_PSTRIDE 33          // ull per path row in sPart
#define PART_DQ (16 * PART_PSTRIDE)  // 528 ull per d-quarter

__device__ int g_mask_mode; // 0 = uint8, 1 = int32, 2 = float32

__global__ void detect_mask_kernel(const unsigned int* __restrict__ w) {
    __shared__ int f_gt1, f_one;
    if (threadIdx.x == 0) { f_gt1 = 0; f_one = 0; }
    __syncthreads();
    unsigned v = w[threadIdx.x];
    if (v == 0x3F800000u)      atomicOr(&f_one, 1);
    else if (v > 1u)           atomicOr(&f_gt1, 1);
    __syncthreads();
    if (threadIdx.x == 0)
        g_mask_mode = f_gt1 ? 0 : (f_one ? 2 : 1);
}

// ---- packed f32x2 helpers (sm_100+) ---------------------------------------
__device__ __forceinline__ unsigned long long pack2(float x, float y) {
    unsigned long long r;
    asm("mov.b64 %0, {%1, %2};" : "=l"(r) : "f"(x), "f"(y));
    return r;
}
__device__ __forceinline__ float2 unpack2(unsigned long long v) {
    float2 r;
    asm("mov.b64 {%0, %1}, %2;" : "=f"(r.x), "=f"(r.y) : "l"(v));
    return r;
}
__device__ __forceinline__ void fma2(unsigned long long& acc,
                                     unsigned long long a,
                                     unsigned long long b) {
    asm("fma.rn.f32x2 %0, %1, %2, %0;" : "+l"(acc) : "l"(a), "l"(b));
}

// Dynamic SMEM layout (float index):
//   sW1   [0     .. 8192)              32 KB  W1[d][j] row-major
//   sAgg  [8192  .. 10304)             16 x 132 floats (padded rows)
//   sPart [10304 .. 14528)             4 dq x 528 ull  (16.5 KB)
//   sWgt  [14528 .. 14544)
//   sVal  [14544 .. 14560)  (int)
static const int SMEM_FLOATS = 14560;

__global__ void __launch_bounds__(512)
pga_kernel(const float* __restrict__ E, const float* __restrict__ W1,
           const float* __restrict__ b1, const float* __restrict__ W2,
           const float* __restrict__ b2, const int* __restrict__ sids,
           const int* __restrict__ eids, const void* __restrict__ maskp,
           float* __restrict__ out, int S) {
    extern __shared__ float smem[];
    float* sW1  = smem;
    float* sAgg = smem + 8192;
    unsigned long long* sPart = (unsigned long long*)(smem + 10304);
    float* sWgt = smem + 14528;
    int*   sVal = (int*)(smem + 14544);

    const int t = threadIdx.x;
    const int lane = t & 31;
    const int warp = t >> 5;

    // W1 -> smem (vectorized)
    {
        const float4* w4 = (const float4*)W1;
        #pragma unroll
        for (int i = t; i < DD * HH / 4; i += 512)
            ((float4*)sW1)[i] = __ldg(w4 + i);
    }
    // Phase C per-thread constants (indexed by lane only)
    const float rb1x = __ldg(b1 + 2 * lane);
    const float rb1y = __ldg(b1 + 2 * lane + 1);
    const float rw2x = __ldg(W2 + 2 * lane);
    const float rw2y = __ldg(W2 + 2 * lane + 1);
    const float bias2 = __ldg(b2);
    const int mode = g_mask_mode;
    __syncthreads();

    // Phase B thread decomposition (fixed per thread)
    const int dq   = t >> 7;        // d-quarter: [dq*32, dq*32+32)
    const int jgrp = (t >> 3) & 15; // j = jgrp*4 .. +3
    const int pgrp = t & 7;         // paths pgrp and pgrp+8

    for (int s = blockIdx.x; s < S; s += gridDim.x) {
        // ---------------- Phase A: gather (warp p <-> path p) --------------
        {
            const int p = warp;
            const int base = (s * PP + p) * KK;
            const int4* ip = (const int4*)(eids + base);
            int4 i0 = __ldg(ip + 0), i1 = __ldg(ip + 1);
            int4 i2 = __ldg(ip + 2), i3 = __ldg(ip + 3);

            unsigned mb = 0;
            if (mode == 0) {
                uint4 mv = __ldg((const uint4*)((const unsigned char*)maskp + base));
                unsigned wds[4] = {mv.x, mv.y, mv.z, mv.w};
                #pragma unroll
                for (int q = 0; q < 4; q++)
                    #pragma unroll
                    for (int b = 0; b < 4; b++)
                        mb |= (((wds[q] >> (8 * b)) & 0xFFu) ? 1u : 0u) << (q * 4 + b);
            } else if (mode == 1) {
                const int4* m4 = (const int4*)((const int*)maskp + base);
                #pragma unroll
                for (int q = 0; q < 4; q++) {
                    int4 mv = __ldg(m4 + q);
                    mb |= (mv.x ? 1u : 0u) << (q * 4 + 0);
                    mb |= (mv.y ? 1u : 0u) << (q * 4 + 1);
                    mb |= (mv.z ? 1u : 0u) << (q * 4 + 2);
                    mb |= (mv.w ? 1u : 0u) << (q * 4 + 3);
                }
            } else {
                const float4* m4 = (const float4*)((const float*)maskp + base);
                #pragma unroll
                for (int q = 0; q < 4; q++) {
                    float4 mv = __ldg(m4 + q);
                    mb |= (mv.x != 0.f ? 1u : 0u) << (q * 4 + 0);
                    mb |= (mv.y != 0.f ? 1u : 0u) << (q * 4 + 1);
                    mb |= (mv.z != 0.f ? 1u : 0u) << (q * 4 + 2);
                    mb |= (mv.w != 0.f ? 1u : 0u) << (q * 4 + 3);
                }
            }
            const int cnt = __popc(mb);

            const float4* E4 = (const float4*)E;
            float4 acc = make_float4(0.f, 0.f, 0.f, 0.f);
            const int idk[16] = {i0.x, i0.y, i0.z, i0.w, i1.x, i1.y, i1.z, i1.w,
                                 i2.x, i2.y, i2.z, i2.w, i3.x, i3.y, i3.z, i3.w};
            #pragma unroll
            for (int k = 0; k < KK; k++) {
                if (mb & (1u << k)) {
                    float4 v = __ldg(E4 + idk[k] * (DD / 4) + lane);
                    acc.x += v.x; acc.y += v.y; acc.z += v.z; acc.w += v.w;
                }
            }
            const float inv = 1.f / (float)(cnt > 0 ? cnt : 1);
            float4 a = make_float4(acc.x * inv, acc.y * inv, acc.z * inv, acc.w * inv);
            ((float4*)(sAgg + p * AGG_STRIDE))[lane] = a;
            if (lane == 0) sVal[p] = (cnt > 0);
        }
        __syncthreads();

        // -------- Phase B: tiled split-K GEMM h[p][j] partials --------------
        // thread: dq (d-quarter), jgrp (4 j's), pgrp (paths pgrp & pgrp+8)
        {
            const float* a0p = sAgg + pgrp * AGG_STRIDE + dq * 32;
            const float* a1p = a0p + 8 * AGG_STRIDE;
            const float* wp  = sW1 + (dq * 32) * HH + jgrp * 4;
            unsigned long long acc00 = 0ull, acc01 = 0ull;
            unsigned long long acc10 = 0ull, acc11 = 0ull;
            #pragma unroll
            for (int step = 0; step < 8; step++) {
                float4 a0 = *(const float4*)(a0p + step * 4);
                float4 a1 = *(const float4*)(a1p + step * 4);
                float av0[4] = {a0.x, a0.y, a0.z, a0.w};
                float av1[4] = {a1.x, a1.y, a1.z, a1.w};
                #pragma unroll
                for (int r = 0; r < 4; r++) {
                    ulonglong2 w = *(const ulonglong2*)(wp + (step * 4 + r) * HH);
                    unsigned long long aa0 = pack2(av0[r], av0[r]);
                    unsigned long long aa1 = pack2(av1[r], av1[r]);
                    fma2(acc00, aa0, w.x); fma2(acc01, aa0, w.y);
                    fma2(acc10, aa1, w.x); fma2(acc11, aa1, w.y);
                }
            }
            unsigned long long* pd = sPart + dq * PART_DQ;
            pd[pgrp       * PART_PSTRIDE + jgrp * 2 + 0] = acc00;
            pd[pgrp       * PART_PSTRIDE + jgrp * 2 + 1] = acc01;
            pd[(pgrp + 8) * PART_PSTRIDE + jgrp * 2 + 0] = acc10;
            pd[(pgrp + 8) * PART_PSTRIDE + jgrp * 2 + 1] = acc11;
        }
        __syncthreads();

        // ------- Phase C: reduce split-K, bias+relu, dot W2, sigmoid -------
        // warp == path p; lane == j-pair index jj (j = 2*jj, 2*jj+1)
        {
            const int p = warp;
            float hx = 0.f, hy = 0.f;
            #pragma unroll
            for (int dqq = 0; dqq < 4; dqq++) {
                float2 v = unpack2(sPart[dqq * PART_DQ + p * PART_PSTRIDE + lane]);
                hx += v.x; hy += v.y;
            }
            float h0 = fmaxf(hx + rb1x, 0.f);
            float h1 = fmaxf(hy + rb1y, 0.f);
            float hw = h0 * rw2x + h1 * rw2y;
            #pragma unroll
            for (int o = 16; o; o >>= 1) hw += __shfl_xor_sync(0xffffffffu, hw, o);
            if (lane == 0) {
                float x = hw + bias2;
                float w = 1.f / (1.f + expf(-x));
                sWgt[p] = sVal[p] ? w : 0.f;
            }
        }
        __syncthreads();

        // -------- Phase D: weighted mean over valid paths + scatter --------
        if (t < DD) {
            float o = 0.f;
            int nv = 0;
            #pragma unroll
            for (int p = 0; p < PP; p++) {
                o += sWgt[p] * sAgg[p * AGG_STRIDE + t];
                nv += sVal[p];
            }
            out[__ldg(sids + s) * DD + t] = o / (float)(nv > 0 ? nv : 1);
        }
        __syncthreads();
    }
}

extern "C" void kernel_launch(void* const* d_in, const int* in_sizes, int n_in,
                              void* d_out, int out_size) {
    const float* E   = (const float*)d_in[0];
    const float* W1  = (const float*)d_in[1];
    const float* b1  = (const float*)d_in[2];
    const float* W2  = (const float*)d_in[3];
    const float* b2  = (const float*)d_in[4];
    const int*   sid = (const int*)d_in[5];
    const int*   eid = (const int*)d_in[6];
    const void*  msk = d_in[7];
    float* out = (float*)d_out;

    const int S = in_sizes[5];

    // Output is poisoned: zero it (rows not in sparse_ids must be 0).
    cudaMemsetAsync(d_out, 0, (size_t)out_size * sizeof(float), 0);

    // Detect mask dtype (deterministic).
    detect_mask_kernel<<<1, 1024>>>((const unsigned int*)msk);

    static const int SMEM_BYTES = SMEM_FLOATS * 4; // 58240 B
    cudaFuncSetAttribute(pga_kernel, cudaFuncAttributeMaxDynamicSharedMemorySize,
                         SMEM_BYTES);

    int grid = 1024;
    if (grid > S) grid = S;
    pga_kernel<<<grid, 512, SMEM_BYTES>>>(E, W1, b1, W2, b2, sid, eid, msk, out, S);
}

// round 4
// speedup vs baseline: 1.8731x; 1.8731x over previous
#include <cuda_runtime.h>
#include <math.h>

// ---------------------------------------------------------------------------
// PathGuidedAggregator: S=8192 nodes x P=16 paths x K=16 endpoints, D=128, H=64
// Round 3: R2's tiled Phase-B GEMM (low crossbar traffic) + occupancy restore:
// __launch_bounds__(512,3) caps regs at 42 -> 3 blocks/SM (R2's 44 regs gave
// only 2 blocks/SM and regressed). Grid = 456 (152 SM x 3) persistent blocks
// for perfect wave balance.
// ---------------------------------------------------------------------------

#define DD 128
#define PP 16
#define KK 16
#define HH 64
#define AGG_STRIDE 132           // floats per sAgg row (pad kills 8-way conflicts)
#define PART_PSTRIDE 33          // ull per path row in sPart
#define PART_DQ (16 * PART_PSTRIDE)  // 528 ull per d-quarter

__device__ int g_mask_mode; // 0 = uint8, 1 = int32, 2 = float32

__global__ void detect_mask_kernel(const unsigned int* __restrict__ w) {
    __shared__ int f_gt1, f_one;
    if (threadIdx.x == 0) { f_gt1 = 0; f_one = 0; }
    __syncthreads();
    unsigned v = w[threadIdx.x];
    if (v == 0x3F800000u)      atomicOr(&f_one, 1);
    else if (v > 1u)           atomicOr(&f_gt1, 1);
    __syncthreads();
    if (threadIdx.x == 0)
        g_mask_mode = f_gt1 ? 0 : (f_one ? 2 : 1);
}

// ---- packed f32x2 helpers (sm_100+) ---------------------------------------
__device__ __forceinline__ unsigned long long pack2(float x, float y) {
    unsigned long long r;
    asm("mov.b64 %0, {%1, %2};" : "=l"(r) : "f"(x), "f"(y));
    return r;
}
__device__ __forceinline__ float2 unpack2(unsigned long long v) {
    float2 r;
    asm("mov.b64 {%0, %1}, %2;" : "=f"(r.x), "=f"(r.y) : "l"(v));
    return r;
}
__device__ __forceinline__ void fma2(unsigned long long& acc,
                                     unsigned long long a,
                                     unsigned long long b) {
    asm("fma.rn.f32x2 %0, %1, %2, %0;" : "+l"(acc) : "l"(a), "l"(b));
}

// Dynamic SMEM layout (float index):
//   sW1   [0     .. 8192)              32 KB  W1[d][j] row-major
//   sAgg  [8192  .. 10304)             16 x 132 floats (padded rows)
//   sPart [10304 .. 14528)             4 dq x 528 ull  (16.5 KB)
//   sWgt  [14528 .. 14544)
//   sVal  [14544 .. 14560)  (int)
static const int SMEM_FLOATS = 14560;

__global__ void __launch_bounds__(512, 3)
pga_kernel(const float* __restrict__ E, const float* __restrict__ W1,
           const float* __restrict__ b1, const float* __restrict__ W2,
           const float* __restrict__ b2, const int* __restrict__ sids,
           const int* __restrict__ eids, const void* __restrict__ maskp,
           float* __restrict__ out, int S) {
    extern __shared__ float smem[];
    float* sW1  = smem;
    float* sAgg = smem + 8192;
    unsigned long long* sPart = (unsigned long long*)(smem + 10304);
    float* sWgt = smem + 14528;
    int*   sVal = (int*)(smem + 14544);

    const int t = threadIdx.x;
    const int lane = t & 31;
    const int warp = t >> 5;

    // W1 -> smem (vectorized)
    {
        const float4* w4 = (const float4*)W1;
        #pragma unroll
        for (int i = t; i < DD * HH / 4; i += 512)
            ((float4*)sW1)[i] = __ldg(w4 + i);
    }
    // Phase C per-thread constants (indexed by lane only)
    const float rb1x = __ldg(b1 + 2 * lane);
    const float rb1y = __ldg(b1 + 2 * lane + 1);
    const float rw2x = __ldg(W2 + 2 * lane);
    const float rw2y = __ldg(W2 + 2 * lane + 1);
    const float bias2 = __ldg(b2);
    const int mode = g_mask_mode;
    __syncthreads();

    // Phase B thread decomposition (fixed per thread)
    const int dq   = t >> 7;        // d-quarter: [dq*32, dq*32+32)
    const int jgrp = (t >> 3) & 15; // j = jgrp*4 .. +3
    const int pgrp = t & 7;         // paths pgrp and pgrp+8

    for (int s = blockIdx.x; s < S; s += gridDim.x) {
        // ---------------- Phase A: gather (warp p <-> path p) --------------
        {
            const int p = warp;
            const int base = (s * PP + p) * KK;
            const int4* ip = (const int4*)(eids + base);
            int4 i0 = __ldg(ip + 0), i1 = __ldg(ip + 1);
            int4 i2 = __ldg(ip + 2), i3 = __ldg(ip + 3);

            unsigned mb = 0;
            if (mode == 0) {
                uint4 mv = __ldg((const uint4*)((const unsigned char*)maskp + base));
                unsigned wds[4] = {mv.x, mv.y, mv.z, mv.w};
                #pragma unroll
                for (int q = 0; q < 4; q++)
                    #pragma unroll
                    for (int b = 0; b < 4; b++)
                        mb |= (((wds[q] >> (8 * b)) & 0xFFu) ? 1u : 0u) << (q * 4 + b);
            } else if (mode == 1) {
                const int4* m4 = (const int4*)((const int*)maskp + base);
                #pragma unroll
                for (int q = 0; q < 4; q++) {
                    int4 mv = __ldg(m4 + q);
                    mb |= (mv.x ? 1u : 0u) << (q * 4 + 0);
                    mb |= (mv.y ? 1u : 0u) << (q * 4 + 1);
                    mb |= (mv.z ? 1u : 0u) << (q * 4 + 2);
                    mb |= (mv.w ? 1u : 0u) << (q * 4 + 3);
                }
            } else {
                const float4* m4 = (const float4*)((const float*)maskp + base);
                #pragma unroll
                for (int q = 0; q < 4; q++) {
                    float4 mv = __ldg(m4 + q);
                    mb |= (mv.x != 0.f ? 1u : 0u) << (q * 4 + 0);
                    mb |= (mv.y != 0.f ? 1u : 0u) << (q * 4 + 1);
                    mb |= (mv.z != 0.f ? 1u : 0u) << (q * 4 + 2);
                    mb |= (mv.w != 0.f ? 1u : 0u) << (q * 4 + 3);
                }
            }
            const int cnt = __popc(mb);

            const float4* E4 = (const float4*)E;
            float4 acc = make_float4(0.f, 0.f, 0.f, 0.f);
            const int idk[16] = {i0.x, i0.y, i0.z, i0.w, i1.x, i1.y, i1.z, i1.w,
                                 i2.x, i2.y, i2.z, i2.w, i3.x, i3.y, i3.z, i3.w};
            #pragma unroll
            for (int k = 0; k < KK; k++) {
                if (mb & (1u << k)) {
                    float4 v = __ldg(E4 + idk[k] * (DD / 4) + lane);
                    acc.x += v.x; acc.y += v.y; acc.z += v.z; acc.w += v.w;
                }
            }
            const float inv = 1.f / (float)(cnt > 0 ? cnt : 1);
            float4 a = make_float4(acc.x * inv, acc.y * inv, acc.z * inv, acc.w * inv);
            ((float4*)(sAgg + p * AGG_STRIDE))[lane] = a;
            if (lane == 0) sVal[p] = (cnt > 0);
        }
        __syncthreads();

        // -------- Phase B: tiled split-K GEMM h[p][j] partials --------------
        // thread: dq (d-quarter), jgrp (4 j's), pgrp (paths pgrp & pgrp+8)
        {
            const float* a0p = sAgg + pgrp * AGG_STRIDE + dq * 32;
            const float* a1p = a0p + 8 * AGG_STRIDE;
            const float* wp  = sW1 + (dq * 32) * HH + jgrp * 4;
            unsigned long long acc00 = 0ull, acc01 = 0ull;
            unsigned long long acc10 = 0ull, acc11 = 0ull;
            #pragma unroll
            for (int step = 0; step < 8; step++) {
                float4 a0 = *(const float4*)(a0p + step * 4);
                float4 a1 = *(const float4*)(a1p + step * 4);
                float av0[4] = {a0.x, a0.y, a0.z, a0.w};
                float av1[4] = {a1.x, a1.y, a1.z, a1.w};
                #pragma unroll
                for (int r = 0; r < 4; r++) {
                    ulonglong2 w = *(const ulonglong2*)(wp + (step * 4 + r) * HH);
                    unsigned long long aa0 = pack2(av0[r], av0[r]);
                    unsigned long long aa1 = pack2(av1[r], av1[r]);
                    fma2(acc00, aa0, w.x); fma2(acc01, aa0, w.y);
                    fma2(acc10, aa1, w.x); fma2(acc11, aa1, w.y);
                }
            }
            unsigned long long* pd = sPart + dq * PART_DQ;
            pd[pgrp       * PART_PSTRIDE + jgrp * 2 + 0] = acc00;
            pd[pgrp       * PART_PSTRIDE + jgrp * 2 + 1] = acc01;
            pd[(pgrp + 8) * PART_PSTRIDE + jgrp * 2 + 0] = acc10;
            pd[(pgrp + 8) * PART_PSTRIDE + jgrp * 2 + 1] = acc11;
        }
        __syncthreads();

        // ------- Phase C: reduce split-K, bias+relu, dot W2, sigmoid -------
        // warp == path p; lane == j-pair index jj (j = 2*jj, 2*jj+1)
        {
            const int p = warp;
            float hx = 0.f, hy = 0.f;
            #pragma unroll
            for (int dqq = 0; dqq < 4; dqq++) {
                float2 v = unpack2(sPart[dqq * PART_DQ + p * PART_PSTRIDE + lane]);
                hx += v.x; hy += v.y;
            }
            float h0 = fmaxf(hx + rb1x, 0.f);
            float h1 = fmaxf(hy + rb1y, 0.f);
            float hw = h0 * rw2x + h1 * rw2y;
            #pragma unroll
            for (int o = 16; o; o >>= 1) hw += __shfl_xor_sync(0xffffffffu, hw, o);
            if (lane == 0) {
                float x = hw + bias2;
                float w = 1.f / (1.f + expf(-x));
                sWgt[p] = sVal[p] ? w : 0.f;
            }
        }
        __syncthreads();

        // -------- Phase D: weighted mean over valid paths + scatter --------
        if (t < DD) {
            float o = 0.f;
            int nv = 0;
            #pragma unroll
            for (int p = 0; p < PP; p++) {
                o += sWgt[p] * sAgg[p * AGG_STRIDE + t];
                nv += sVal[p];
            }
            out[__ldg(sids + s) * DD + t] = o / (float)(nv > 0 ? nv : 1);
        }
        __syncthreads();
    }
}

extern "C" void kernel_launch(void* const* d_in, const int* in_sizes, int n_in,
                              void* d_out, int out_size) {
    const float* E   = (const float*)d_in[0];
    const float* W1  = (const float*)d_in[1];
    const float* b1  = (const float*)d_in[2];
    const float* W2  = (const float*)d_in[3];
    const float* b2  = (const float*)d_in[4];
    const int*   sid = (const int*)d_in[5];
    const int*   eid = (const int*)d_in[6];
    const void*  msk = d_in[7];
    float* out = (float*)d_out;

    const int S = in_sizes[5];

    // Output is poisoned: zero it (rows not in sparse_ids must be 0).
    cudaMemsetAsync(d_out, 0, (size_t)out_size * sizeof(float), 0);

    // Detect mask dtype (deterministic).
    detect_mask_kernel<<<1, 1024>>>((const unsigned int*)msk);

    static const int SMEM_BYTES = SMEM_FLOATS * 4; // 58240 B
    cudaFuncSetAttribute(pga_kernel, cudaFuncAttributeMaxDynamicSharedMemorySize,
                         SMEM_BYTES);

    // 152 SMs x 3 blocks/SM = 456 persistent blocks (single balanced wave).
    int grid = 456;
    if (grid > S) grid = S;
    pga_kernel<<<grid, 512, SMEM_BYTES>>>(E, W1, b1, W2, b2, sid, eid, msk, out, S);
}